// round 15
// baseline (speedup 1.0000x reference)
#include <cuda_runtime.h>
#include <cuda_bf16.h>
#include <math.h>
#include <stdint.h>

// Problem constants (fixed by setup_inputs)
#define T_STEPS 512
#define BATCH   64
#define HID     512
#define GDIM    2048   // 4*H
#define DDIM    512
#define MROWS   (T_STEPS * BATCH)   // 32768

typedef unsigned long long ull;

// ---- scratch (device globals: allocation-free rule) ----
__device__ float g_xproj[(size_t)MROWS * GDIM];                 // 268 MB
__device__ __align__(16) __nv_bfloat16 g_xhi[(size_t)MROWS * DDIM];
__device__ __align__(16) __nv_bfloat16 g_xlo[(size_t)MROWS * DDIM];
__device__ __align__(16) __nv_bfloat16 g_wthi[(size_t)GDIM * DDIM];
__device__ __align__(16) __nv_bfloat16 g_wtlo[(size_t)GDIM * DDIM];
__device__ __align__(16) __nv_bfloat16 g_hhi[BATCH * HID];
__device__ __align__(16) __nv_bfloat16 g_hlo[BATCH * HID];
__device__ unsigned int g_bar_count = 0;
__device__ unsigned int g_bar_gen   = 0;

// fast activations: MUFU-based, rel err ~1e-6
__device__ __forceinline__ float fsig(float x) {
    return __fdividef(1.0f, 1.0f + __expf(-x));
}
__device__ __forceinline__ float ftanh_(float x) {
    float t = __expf(-2.0f * fabsf(x));
    float r = __fdividef(1.0f - t, 1.0f + t);
    return copysignf(r, x);
}

__device__ __forceinline__ uint32_t smem_u32(const void* p) {
    uint32_t a;
    asm("{ .reg .u64 t; cvta.to.shared.u64 t, %1; cvt.u32.u64 %0, t; }" : "=r"(a) : "l"(p));
    return a;
}

#define CP_ASYNC16(dst, src) \
    asm volatile("cp.async.cg.shared.global [%0], [%1], 16;" :: "r"(dst), "l"(src))
#define CP_COMMIT()   asm volatile("cp.async.commit_group;" ::: "memory")
#define CP_WAIT(n)    asm volatile("cp.async.wait_group %0;" :: "n"(n) : "memory")

#define LDSM_X4(r0, r1, r2, r3, a) \
    asm volatile("ldmatrix.sync.aligned.m8n8.x4.shared.b16 {%0,%1,%2,%3}, [%4];" \
                 : "=r"(r0), "=r"(r1), "=r"(r2), "=r"(r3) : "r"(a))
#define LDSM_X2(r0, r1, a) \
    asm volatile("ldmatrix.sync.aligned.m8n8.x2.shared.b16 {%0,%1}, [%2];" \
                 : "=r"(r0), "=r"(r1) : "r"(a))
#define MMA16816(d, a, b0, b1) \
    asm volatile("mma.sync.aligned.m16n8k16.row.col.f32.bf16.bf16.f32 " \
                 "{%0,%1,%2,%3}, {%4,%5,%6,%7}, {%8,%9}, {%0,%1,%2,%3};" \
                 : "+f"((d)[0]), "+f"((d)[1]), "+f"((d)[2]), "+f"((d)[3]) \
                 : "r"((a)[0]), "r"((a)[1]), "r"((a)[2]), "r"((a)[3]), "r"(b0), "r"(b1))

// =====================================================================
// k_convert_x / k_convert_w (unchanged)
// =====================================================================
__global__ __launch_bounds__(256) void k_convert_x(const float* __restrict__ x) {
    size_t i = (size_t)blockIdx.x * 256 + threadIdx.x;
    float4 v = ((const float4*)x)[i];
    __nv_bfloat162 h01 = __float22bfloat162_rn(make_float2(v.x, v.y));
    __nv_bfloat162 h23 = __float22bfloat162_rn(make_float2(v.z, v.w));
    float2 f01 = __bfloat1622float2(h01);
    float2 f23 = __bfloat1622float2(h23);
    __nv_bfloat162 l01 = __float22bfloat162_rn(make_float2(v.x - f01.x, v.y - f01.y));
    __nv_bfloat162 l23 = __float22bfloat162_rn(make_float2(v.z - f23.x, v.w - f23.y));
    uint2 hv, lv;
    hv.x = *(uint32_t*)&h01; hv.y = *(uint32_t*)&h23;
    lv.x = *(uint32_t*)&l01; lv.y = *(uint32_t*)&l23;
    ((uint2*)g_xhi)[i] = hv;
    ((uint2*)g_xlo)[i] = lv;
}

__global__ __launch_bounds__(256) void k_convert_w(const float* __restrict__ Wx) {
    __shared__ float tile[32][33];
    const int n0 = blockIdx.x * 32;
    const int k0 = blockIdx.y * 32;
    const int c = threadIdx.x & 31, r = threadIdx.x >> 5;
#pragma unroll
    for (int i = 0; i < 4; i++)
        tile[r + i * 8][c] = Wx[(size_t)(k0 + r + i * 8) * GDIM + n0 + c];
    __syncthreads();
#pragma unroll
    for (int i = 0; i < 4; i++) {
        int nn = r + i * 8;
        float v = tile[c][nn];
        __nv_bfloat16 hi = __float2bfloat16_rn(v);
        g_wthi[(size_t)(n0 + nn) * DDIM + k0 + c] = hi;
        g_wtlo[(size_t)(n0 + nn) * DDIM + k0 + c] =
            __float2bfloat16_rn(v - __bfloat162float(hi));
    }
}

// =====================================================================
// k_xproj_hmma: 3-stage cp.async pipeline (unchanged from round 13)
// =====================================================================
#define XSTAGE 32768
#define XNST   3
#define XSMEM  (XNST * XSTAGE)

__global__ __launch_bounds__(256, 2) void k_xproj_hmma(const float* __restrict__ bias) {
    extern __shared__ char xsm[];
    const uint32_t smb = smem_u32(xsm);
    const int tid = threadIdx.x, lane = tid & 31, wid = tid >> 5;
    const int n0 = blockIdx.x * 128;
    const int m0 = blockIdx.y * 128;
    const int wm = wid & 3, wn = wid >> 2;

    const int sr = tid >> 1;
    const int spl = tid & 1;
    const uint32_t sdst0 = (uint32_t)(sr * 128);
    const int sswz = sr & 7;

    float acc[2][8][4];
#pragma unroll
    for (int mi = 0; mi < 2; mi++)
#pragma unroll
        for (int g = 0; g < 8; g++)
#pragma unroll
            for (int q = 0; q < 4; q++) acc[mi][g][q] = 0.0f;

    const __nv_bfloat16* asrc = (spl ? g_xlo : g_xhi) + (size_t)(m0 + sr) * DDIM;
    const __nv_bfloat16* bsrc = (spl ? g_wtlo : g_wthi) + (size_t)(n0 + sr) * DDIM;

#pragma unroll
    for (int ps = 0; ps < 2; ps++) {
        uint32_t buf = smb + (uint32_t)ps * XSTAGE;
#pragma unroll
        for (int jj = 0; jj < 4; jj++) {
            int j = spl * 4 + jj;
            uint32_t dA = buf + sdst0 + (uint32_t)((j ^ sswz) << 4);
            CP_ASYNC16(dA, asrc + ps * 32 + jj * 8);
            CP_ASYNC16(dA + 16384, bsrc + ps * 32 + jj * 8);
        }
        CP_COMMIT();
    }

    for (int s = 0; s < 16; s++) {
        if (s < 15) { CP_WAIT(1); } else { CP_WAIT(0); }
        __syncthreads();

        if (s < 14) {
            int k0 = (s + 2) * 32;
            uint32_t buf = smb + (uint32_t)((s + 2) % XNST) * XSTAGE;
#pragma unroll
            for (int jj = 0; jj < 4; jj++) {
                int j = spl * 4 + jj;
                uint32_t dA = buf + sdst0 + (uint32_t)((j ^ sswz) << 4);
                CP_ASYNC16(dA, asrc + k0 + jj * 8);
                CP_ASYNC16(dA + 16384, bsrc + k0 + jj * 8);
            }
            CP_COMMIT();
        }

        const uint32_t Ab = smb + (uint32_t)(s % XNST) * XSTAGE;
        const uint32_t Bb = Ab + 16384;
#pragma unroll
        for (int kk = 0; kk < 2; kk++) {
            uint32_t ah[2][4], al[2][4];
#pragma unroll
            for (int mi = 0; mi < 2; mi++) {
                int ar = wm * 32 + mi * 16 + (lane & 15);
                int uh = kk * 2 + ((lane >> 4) & 1);
                uint32_t base = Ab + (uint32_t)(ar * 128);
                int s7 = ar & 7;
                LDSM_X4(ah[mi][0], ah[mi][1], ah[mi][2], ah[mi][3],
                        base + (uint32_t)((uh ^ s7) << 4));
                LDSM_X4(al[mi][0], al[mi][1], al[mi][2], al[mi][3],
                        base + (uint32_t)(((uh + 4) ^ s7) << 4));
            }
#pragma unroll
            for (int g = 0; g < 8; g++) {
                int br = wn * 64 + g * 8 + (lane & 7);
                int ub = kk * 2 + ((lane >> 3) & 1);
                uint32_t base = Bb + (uint32_t)(br * 128);
                int s7 = br & 7;
                uint32_t b0, b1, c0, c1;
                LDSM_X2(b0, b1, base + (uint32_t)((ub ^ s7) << 4));
                LDSM_X2(c0, c1, base + (uint32_t)(((ub + 4) ^ s7) << 4));
#pragma unroll
                for (int mi = 0; mi < 2; mi++) {
                    MMA16816(acc[mi][g], ah[mi], b0, b1);
                    MMA16816(acc[mi][g], al[mi], b0, b1);
                    MMA16816(acc[mi][g], ah[mi], c0, c1);
                }
            }
        }
    }

#pragma unroll
    for (int mi = 0; mi < 2; mi++) {
        int gr = m0 + wm * 32 + mi * 16 + (lane >> 2);
#pragma unroll
        for (int g = 0; g < 8; g++) {
            int gc = n0 + wn * 64 + g * 8 + (lane & 3) * 2;
            float2 bb = *(const float2*)(bias + gc);
            float2 v0 = {acc[mi][g][0] + bb.x, acc[mi][g][1] + bb.y};
            float2 v1 = {acc[mi][g][2] + bb.x, acc[mi][g][3] + bb.y};
            *(float2*)(g_xproj + (size_t)gr * GDIM + gc)       = v0;
            *(float2*)(g_xproj + (size_t)(gr + 8) * GDIM + gc) = v1;
        }
    }
}

// =====================================================================
// k_rnn: round-14 base; round-15 delta ONLY: two-phase staging/MMA
// overlap. hi plane committed separately; terms 0&2 (A-hi) run while
// the lo plane is still in flight; term 1 (A-lo) runs after CP_WAIT(0).
// =====================================================================
#define NCTA 128
#define NTHR 512

#define OFF_A  0        // 64 rows x 2048B = 131072
#define OFF_B  131072   // 16 rows x 2048B = 32768
#define OFF_G  163840   // gates 64 x 17 floats = 4352
#define SMEM2  168448

__device__ __forceinline__ uint32_t swz(int row, int kbyte) {
    return (uint32_t)(row * 2048) + ((((uint32_t)kbyte >> 4) ^ (uint32_t)(row & 7)) << 4)
         + ((uint32_t)kbyte & 15u);
}

__global__ __launch_bounds__(NTHR, 1) void k_rnn(const float* __restrict__ h0,
                                                 const float* __restrict__ c0,
                                                 const float* __restrict__ mask,
                                                 const float* __restrict__ Wh,
                                                 float* __restrict__ out) {
    extern __shared__ char smraw[];
    const uint32_t smb = smem_u32(smraw);
    float* gates_s = (float*)(smraw + OFF_G);
    const int tid = threadIdx.x, lane = tid & 31, wid = tid >> 5;
    const int cta = blockIdx.x, hc0 = cta * 4;

    // ---- Wh slice -> B smem, split-bf16 (hi at kbyte<1024, lo >=1024) ----
#pragma unroll 4
    for (int it = 0; it < 32; it++) {
        int e = tid + it * NTHR;
        int n = e >> 10, k = e & 1023;
        int gcol = (n >> 2) * HID + hc0 + (n & 3);
        float v = Wh[(size_t)(k & 511) * GDIM + gcol];
        __nv_bfloat16 hi = __float2bfloat16_rn(v);
        __nv_bfloat16 bv = (k < 512) ? hi : __float2bfloat16_rn(v - __bfloat162float(hi));
        *(__nv_bfloat16*)(smraw + OFF_B + swz(n, k * 2)) = bv;
    }

    // MMA warp coords (wid < 8)
    const int mt = wid & 3, nt = wid >> 2;
    const int ar = mt * 16 + (lane & 15);
    const uint32_t aRowBase = smb + OFF_A + (uint32_t)ar * 2048;
    const uint32_t sA = (uint32_t)(ar & 7) << 4;
    const uint32_t aHi = (uint32_t)((lane >> 4) & 1) << 4;
    const int br = nt * 8 + (lane & 7);
    const uint32_t bRowBase = smb + OFF_B + (uint32_t)br * 2048;
    const uint32_t sB = (uint32_t)(br & 7) << 4;
    const uint32_t bQ = (uint32_t)((lane >> 3) & 3) << 4;   // x4: 4 groups of 16B

    // staging coords: one row per 8 threads, 16 x 16B units each (linear)
    const int strow = tid >> 3;
    const int stj   = tid & 7;
    const uint32_t stdst0 = smb + OFF_A + (uint32_t)(strow * 2048)
                          + ((uint32_t)(stj ^ (strow & 7)) << 4);
    const __nv_bfloat16* sthi = g_hhi + strow * HID + stj * 8;
    const __nv_bfloat16* stlo = g_hlo + strow * HID + stj * 8;

    // update mapping (first 256 threads)
    const int ub = tid >> 2;
    const int uj = tid & 3;
    float c_reg = 0.0f, h_last = 0.0f;
    if (tid < 256) c_reg = c0[ub * HID + hc0 + uj];

    unsigned int bar_target = 0;
    if (tid == 0) bar_target = *((volatile unsigned int*)&g_bar_gen);
    __syncthreads();

    for (int t = 0; t < T_STEPS; t++) {
        // xp prefetch (DRAM latency overlaps staging + MMA)
        float xpi = 0, xpf = 0, xpg = 0, xpo = 0;
        if (tid < 256) {
            const float* xp = g_xproj + ((size_t)t * BATCH + ub) * GDIM + hc0 + uj;
            xpi = xp[0]; xpf = xp[HID]; xpg = xp[2 * HID]; xpo = xp[3 * HID];
        }
        const float* mrow = mask + t * BATCH;
        float mval = __ldg(&mrow[strow]);

        // ---- stage h: hi plane group, then lo plane group ----
        if (t == 0) {
#pragma unroll
            for (int it = 0; it < 16; it++) {
                int idx = tid + it * NTHR;
                int row = idx >> 7, f4 = idx & 127;
                float4 v = *(const float4*)(h0 + (size_t)row * HID + f4 * 4);
                float kp = 1.0f - __ldg(&mrow[row]);
                v.x *= kp; v.y *= kp; v.z *= kp; v.w *= kp;
                __nv_bfloat162 h01 = __float22bfloat162_rn(make_float2(v.x, v.y));
                __nv_bfloat162 h23 = __float22bfloat162_rn(make_float2(v.z, v.w));
                float2 f01 = __bfloat1622float2(h01);
                float2 f23 = __bfloat1622float2(h23);
                __nv_bfloat162 l01 = __float22bfloat162_rn(make_float2(v.x - f01.x, v.y - f01.y));
                __nv_bfloat162 l23 = __float22bfloat162_rn(make_float2(v.z - f23.x, v.w - f23.y));
                uint2 hv, lv;
                hv.x = *(uint32_t*)&h01; hv.y = *(uint32_t*)&h23;
                lv.x = *(uint32_t*)&l01; lv.y = *(uint32_t*)&l23;
                *(uint2*)(smraw + OFF_A + swz(row, f4 * 8))        = hv;
                *(uint2*)(smraw + OFF_A + swz(row, 1024 + f4 * 8)) = lv;
            }
        } else {
            uint32_t d = stdst0;
#pragma unroll
            for (int i = 0; i < 8; i++) { CP_ASYNC16(d, sthi + i * 64); d += 128; }
            CP_COMMIT();
#pragma unroll
            for (int i = 0; i < 8; i++) { CP_ASYNC16(d, stlo + i * 64); d += 128; }
            CP_COMMIT();
            CP_WAIT(1);                      // hi plane resident
            if (mval != 0.0f) {
                uint32_t dz = stdst0;
#pragma unroll
                for (int i = 0; i < 8; i++) {
                    asm volatile("st.shared.v4.b32 [%0], {%1,%1,%1,%1};" :: "r"(dz), "r"(0u));
                    dz += 128;
                }
            }
        }
        __syncthreads();

        // ---- MMA phase A: terms 0 (hi*Whi) and 2 (hi*Wlo) — A-hi only ----
        float d0[4] = {0.f, 0.f, 0.f, 0.f};
        float d1[4] = {0.f, 0.f, 0.f, 0.f};
        if (wid < 8) {
#pragma unroll
            for (int bo = 0; bo < 2; bo++) {
                const uint32_t bOff = bo ? 1024u : 0u;
#pragma unroll 4
                for (int kc = 0; kc < 32; kc += 2) {
                    uint32_t kb = (uint32_t)kc << 5;
                    uint32_t a0r[4], a1r[4], b0, b1, b2, b3;
                    LDSM_X4(a0r[0], a0r[1], a0r[2], a0r[3],
                            aRowBase + ((kb + aHi) ^ sA));
                    LDSM_X4(a1r[0], a1r[1], a1r[2], a1r[3],
                            aRowBase + ((kb + 32u + aHi) ^ sA));
                    LDSM_X4(b0, b1, b2, b3,
                            bRowBase + ((bOff + kb + bQ) ^ sB));
                    MMA16816(d0, a0r, b0, b1);
                    MMA16816(d1, a1r, b2, b3);
                }
            }
        }

        // ---- lo plane: wait, mask-zero, sync ----
        if (t > 0) {
            CP_WAIT(0);
            if (mval != 0.0f) {
                uint32_t dz = stdst0 + 1024u;
#pragma unroll
                for (int i = 0; i < 8; i++) {
                    asm volatile("st.shared.v4.b32 [%0], {%1,%1,%1,%1};" :: "r"(dz), "r"(0u));
                    dz += 128;
                }
            }
        }
        __syncthreads();

        // ---- MMA phase B: term 1 (lo*Whi) — A-lo ----
        if (wid < 8) {
#pragma unroll 4
            for (int kc = 0; kc < 32; kc += 2) {
                uint32_t kb = (uint32_t)kc << 5;
                uint32_t a0r[4], a1r[4], b0, b1, b2, b3;
                LDSM_X4(a0r[0], a0r[1], a0r[2], a0r[3],
                        aRowBase + ((1024u + kb + aHi) ^ sA));
                LDSM_X4(a1r[0], a1r[1], a1r[2], a1r[3],
                        aRowBase + ((1024u + kb + 32u + aHi) ^ sA));
                LDSM_X4(b0, b1, b2, b3,
                        bRowBase + ((kb + bQ) ^ sB));
                MMA16816(d0, a0r, b0, b1);
                MMA16816(d1, a1r, b2, b3);
            }
#pragma unroll
            for (int q = 0; q < 4; q++) d0[q] += d1[q];
            int gr = mt * 16 + (lane >> 2);
            int gc = nt * 8 + (lane & 3) * 2;
            gates_s[gr * 17 + gc]           = d0[0];
            gates_s[gr * 17 + gc + 1]       = d0[1];
            gates_s[(gr + 8) * 17 + gc]     = d0[2];
            gates_s[(gr + 8) * 17 + gc + 1] = d0[3];
        }
        __syncthreads();

        // ---- LSTM cell update (threads 0..255, fast activations) ----
        if (tid < 256) {
            float kp = 1.0f - __ldg(&mrow[ub]);
            float gi = gates_s[ub * 17 + 0  + uj] + xpi;
            float gf = gates_s[ub * 17 + 4  + uj] + xpf;
            float gg = gates_s[ub * 17 + 8  + uj] + xpg;
            float go = gates_s[ub * 17 + 12 + uj] + xpo;
            float cprev = c_reg * kp;
            float cn = fsig(gf) * cprev + fsig(gi) * ftanh_(gg);
            float hn = fsig(go) * ftanh_(cn);
            c_reg = cn;
            h_last = hn;
            int hcol = hc0 + uj;
            out[(size_t)t * BATCH * HID + ub * HID + hcol] = hn;
            __nv_bfloat16 hh = __float2bfloat16_rn(hn);
            g_hhi[ub * HID + hcol] = hh;
            g_hlo[ub * HID + hcol] = __float2bfloat16_rn(hn - __bfloat162float(hh));
        }

        // ---- grid barrier: central counter, tid0-only polling ----
        __syncthreads();
        if (tid == 0) {
            bar_target += 1;
            unsigned int old;
            asm volatile("atom.add.acq_rel.gpu.u32 %0, [%1], 1;"
                         : "=r"(old) : "l"(&g_bar_count) : "memory");
            if (old == NCTA - 1) {
                asm volatile("st.relaxed.gpu.u32 [%0], 0;" :: "l"(&g_bar_count) : "memory");
                asm volatile("red.add.release.gpu.u32 [%0], 1;" :: "l"(&g_bar_gen) : "memory");
            } else {
                unsigned int g;
                while (1) {
                    asm volatile("ld.acquire.gpu.u32 %0, [%1];"
                                 : "=r"(g) : "l"(&g_bar_gen) : "memory");
                    if ((int)(g - bar_target) >= 0) break;
                    __nanosleep(20);
                }
            }
        }
        __syncthreads();
    }

    // Finals
    if (tid < 256) {
        float* hfin = out + (size_t)T_STEPS * BATCH * HID;
        float* cfin = hfin + BATCH * HID;
        hfin[ub * HID + hc0 + uj] = h_last;
        cfin[ub * HID + hc0 + uj] = c_reg;
    }
}

// =====================================================================
extern "C" void kernel_launch(void* const* d_in, const int* in_sizes, int n_in,
                              void* d_out, int out_size) {
    (void)in_sizes; (void)n_in; (void)out_size;
    const float* x    = (const float*)d_in[0];
    const float* h0   = (const float*)d_in[1];
    const float* c0   = (const float*)d_in[2];
    const float* mask = (const float*)d_in[3];
    const float* Wx   = (const float*)d_in[4];
    const float* Wh   = (const float*)d_in[5];
    const float* b    = (const float*)d_in[6];
    float* out = (float*)d_out;

    k_convert_x<<<MROWS * DDIM / 4 / 256, 256>>>(x);
    k_convert_w<<<dim3(GDIM / 32, DDIM / 32), 256>>>(Wx);

    cudaFuncSetAttribute(k_xproj_hmma, cudaFuncAttributeMaxDynamicSharedMemorySize, XSMEM);
    k_xproj_hmma<<<dim3(GDIM / 128, MROWS / 128), 256, XSMEM>>>(b);

    cudaFuncSetAttribute(k_rnn, cudaFuncAttributeMaxDynamicSharedMemorySize, SMEM2);
    k_rnn<<<NCTA, NTHR, SMEM2>>>(h0, c0, mask, Wh, out);
}

// round 17
// speedup vs baseline: 1.0088x; 1.0088x over previous
#include <cuda_runtime.h>
#include <cuda_bf16.h>
#include <math.h>
#include <stdint.h>

// Problem constants (fixed by setup_inputs)
#define T_STEPS 512
#define BATCH   64
#define HID     512
#define GDIM    2048   // 4*H
#define DDIM    512
#define MROWS   (T_STEPS * BATCH)   // 32768

typedef unsigned long long ull;

// ---- scratch (device globals: allocation-free rule) ----
__device__ float g_xproj[(size_t)MROWS * GDIM];                 // 268 MB
__device__ __align__(16) __nv_bfloat16 g_xhi[(size_t)MROWS * DDIM];
__device__ __align__(16) __nv_bfloat16 g_xlo[(size_t)MROWS * DDIM];
__device__ __align__(16) __nv_bfloat16 g_wthi[(size_t)GDIM * DDIM];
__device__ __align__(16) __nv_bfloat16 g_wtlo[(size_t)GDIM * DDIM];
__device__ __align__(16) __nv_bfloat16 g_hhi[BATCH * HID];
__device__ __align__(16) __nv_bfloat16 g_hlo[BATCH * HID];
__device__ unsigned int g_bar_count = 0;
__device__ unsigned int g_bar_gen   = 0;

// fast activations: MUFU-based, rel err ~1e-6
__device__ __forceinline__ float fsig(float x) {
    return __fdividef(1.0f, 1.0f + __expf(-x));
}
__device__ __forceinline__ float ftanh_(float x) {
    float t = __expf(-2.0f * fabsf(x));
    float r = __fdividef(1.0f - t, 1.0f + t);
    return copysignf(r, x);
}

__device__ __forceinline__ uint32_t smem_u32(const void* p) {
    uint32_t a;
    asm("{ .reg .u64 t; cvta.to.shared.u64 t, %1; cvt.u32.u64 %0, t; }" : "=r"(a) : "l"(p));
    return a;
}

#define CP_ASYNC16(dst, src) \
    asm volatile("cp.async.cg.shared.global [%0], [%1], 16;" :: "r"(dst), "l"(src))
#define CP_COMMIT()   asm volatile("cp.async.commit_group;" ::: "memory")
#define CP_WAIT(n)    asm volatile("cp.async.wait_group %0;" :: "n"(n) : "memory")

#define LDSM_X4(r0, r1, r2, r3, a) \
    asm volatile("ldmatrix.sync.aligned.m8n8.x4.shared.b16 {%0,%1,%2,%3}, [%4];" \
                 : "=r"(r0), "=r"(r1), "=r"(r2), "=r"(r3) : "r"(a))
#define LDSM_X2(r0, r1, a) \
    asm volatile("ldmatrix.sync.aligned.m8n8.x2.shared.b16 {%0,%1}, [%2];" \
                 : "=r"(r0), "=r"(r1) : "r"(a))
#define MMA16816(d, a, b0, b1) \
    asm volatile("mma.sync.aligned.m16n8k16.row.col.f32.bf16.bf16.f32 " \
                 "{%0,%1,%2,%3}, {%4,%5,%6,%7}, {%8,%9}, {%0,%1,%2,%3};" \
                 : "+f"((d)[0]), "+f"((d)[1]), "+f"((d)[2]), "+f"((d)[3]) \
                 : "r"((a)[0]), "r"((a)[1]), "r"((a)[2]), "r"((a)[3]), "r"(b0), "r"(b1))

// =====================================================================
// k_convert_x / k_convert_w (round-14 versions, both planes)
// =====================================================================
__global__ __launch_bounds__(256) void k_convert_x(const float* __restrict__ x) {
    size_t i = (size_t)blockIdx.x * 256 + threadIdx.x;
    float4 v = ((const float4*)x)[i];
    __nv_bfloat162 h01 = __float22bfloat162_rn(make_float2(v.x, v.y));
    __nv_bfloat162 h23 = __float22bfloat162_rn(make_float2(v.z, v.w));
    float2 f01 = __bfloat1622float2(h01);
    float2 f23 = __bfloat1622float2(h23);
    __nv_bfloat162 l01 = __float22bfloat162_rn(make_float2(v.x - f01.x, v.y - f01.y));
    __nv_bfloat162 l23 = __float22bfloat162_rn(make_float2(v.z - f23.x, v.w - f23.y));
    uint2 hv, lv;
    hv.x = *(uint32_t*)&h01; hv.y = *(uint32_t*)&h23;
    lv.x = *(uint32_t*)&l01; lv.y = *(uint32_t*)&l23;
    ((uint2*)g_xhi)[i] = hv;
    ((uint2*)g_xlo)[i] = lv;
}

__global__ __launch_bounds__(256) void k_convert_w(const float* __restrict__ Wx) {
    __shared__ float tile[32][33];
    const int n0 = blockIdx.x * 32;
    const int k0 = blockIdx.y * 32;
    const int c = threadIdx.x & 31, r = threadIdx.x >> 5;
#pragma unroll
    for (int i = 0; i < 4; i++)
        tile[r + i * 8][c] = Wx[(size_t)(k0 + r + i * 8) * GDIM + n0 + c];
    __syncthreads();
#pragma unroll
    for (int i = 0; i < 4; i++) {
        int nn = r + i * 8;
        float v = tile[c][nn];
        __nv_bfloat16 hi = __float2bfloat16_rn(v);
        g_wthi[(size_t)(n0 + nn) * DDIM + k0 + c] = hi;
        g_wtlo[(size_t)(n0 + nn) * DDIM + k0 + c] =
            __float2bfloat16_rn(v - __bfloat162float(hi));
    }
}

// =====================================================================
// k_xproj_hmma: 3-stage cp.async pipeline, THREE terms (round-14 exact)
// =====================================================================
#define XSTAGE 32768
#define XNST   3
#define XSMEM  (XNST * XSTAGE)

__global__ __launch_bounds__(256, 2) void k_xproj_hmma(const float* __restrict__ bias) {
    extern __shared__ char xsm[];
    const uint32_t smb = smem_u32(xsm);
    const int tid = threadIdx.x, lane = tid & 31, wid = tid >> 5;
    const int n0 = blockIdx.x * 128;
    const int m0 = blockIdx.y * 128;
    const int wm = wid & 3, wn = wid >> 2;

    const int sr = tid >> 1;
    const int spl = tid & 1;
    const uint32_t sdst0 = (uint32_t)(sr * 128);
    const int sswz = sr & 7;

    float acc[2][8][4];
#pragma unroll
    for (int mi = 0; mi < 2; mi++)
#pragma unroll
        for (int g = 0; g < 8; g++)
#pragma unroll
            for (int q = 0; q < 4; q++) acc[mi][g][q] = 0.0f;

    const __nv_bfloat16* asrc = (spl ? g_xlo : g_xhi) + (size_t)(m0 + sr) * DDIM;
    const __nv_bfloat16* bsrc = (spl ? g_wtlo : g_wthi) + (size_t)(n0 + sr) * DDIM;

#pragma unroll
    for (int ps = 0; ps < 2; ps++) {
        uint32_t buf = smb + (uint32_t)ps * XSTAGE;
#pragma unroll
        for (int jj = 0; jj < 4; jj++) {
            int j = spl * 4 + jj;
            uint32_t dA = buf + sdst0 + (uint32_t)((j ^ sswz) << 4);
            CP_ASYNC16(dA, asrc + ps * 32 + jj * 8);
            CP_ASYNC16(dA + 16384, bsrc + ps * 32 + jj * 8);
        }
        CP_COMMIT();
    }

    for (int s = 0; s < 16; s++) {
        if (s < 15) { CP_WAIT(1); } else { CP_WAIT(0); }
        __syncthreads();

        if (s < 14) {
            int k0 = (s + 2) * 32;
            uint32_t buf = smb + (uint32_t)((s + 2) % XNST) * XSTAGE;
#pragma unroll
            for (int jj = 0; jj < 4; jj++) {
                int j = spl * 4 + jj;
                uint32_t dA = buf + sdst0 + (uint32_t)((j ^ sswz) << 4);
                CP_ASYNC16(dA, asrc + k0 + jj * 8);
                CP_ASYNC16(dA + 16384, bsrc + k0 + jj * 8);
            }
            CP_COMMIT();
        }

        const uint32_t Ab = smb + (uint32_t)(s % XNST) * XSTAGE;
        const uint32_t Bb = Ab + 16384;
#pragma unroll
        for (int kk = 0; kk < 2; kk++) {
            uint32_t ah[2][4], al[2][4];
#pragma unroll
            for (int mi = 0; mi < 2; mi++) {
                int ar = wm * 32 + mi * 16 + (lane & 15);
                int uh = kk * 2 + ((lane >> 4) & 1);
                uint32_t base = Ab + (uint32_t)(ar * 128);
                int s7 = ar & 7;
                LDSM_X4(ah[mi][0], ah[mi][1], ah[mi][2], ah[mi][3],
                        base + (uint32_t)((uh ^ s7) << 4));
                LDSM_X4(al[mi][0], al[mi][1], al[mi][2], al[mi][3],
                        base + (uint32_t)(((uh + 4) ^ s7) << 4));
            }
#pragma unroll
            for (int g = 0; g < 8; g++) {
                int br = wn * 64 + g * 8 + (lane & 7);
                int ub = kk * 2 + ((lane >> 3) & 1);
                uint32_t base = Bb + (uint32_t)(br * 128);
                int s7 = br & 7;
                uint32_t b0, b1, c0, c1;
                LDSM_X2(b0, b1, base + (uint32_t)((ub ^ s7) << 4));
                LDSM_X2(c0, c1, base + (uint32_t)(((ub + 4) ^ s7) << 4));
#pragma unroll
                for (int mi = 0; mi < 2; mi++) {
                    MMA16816(acc[mi][g], ah[mi], b0, b1);
                    MMA16816(acc[mi][g], al[mi], b0, b1);
                    MMA16816(acc[mi][g], ah[mi], c0, c1);
                }
            }
        }
    }

#pragma unroll
    for (int mi = 0; mi < 2; mi++) {
        int gr = m0 + wm * 32 + mi * 16 + (lane >> 2);
#pragma unroll
        for (int g = 0; g < 8; g++) {
            int gc = n0 + wn * 64 + g * 8 + (lane & 3) * 2;
            float2 bb = *(const float2*)(bias + gc);
            float2 v0 = {acc[mi][g][0] + bb.x, acc[mi][g][1] + bb.y};
            float2 v1 = {acc[mi][g][2] + bb.x, acc[mi][g][3] + bb.y};
            *(float2*)(g_xproj + (size_t)gr * GDIM + gc)       = v0;
            *(float2*)(g_xproj + (size_t)(gr + 8) * GDIM + gc) = v1;
        }
    }
}

// =====================================================================
// k_rnn: round-14 base; round-17 delta ONLY: `out` stores are deferred
// past the grid barrier (written during the next iteration; last one
// after the loop). Removes 2KB/CTA of global-store drain from the
// release path of the arrival atomic.
// =====================================================================
#define NCTA 128
#define NTHR 512

#define OFF_A  0        // 64 rows x 2048B = 131072
#define OFF_B  131072   // 16 rows x 2048B = 32768
#define OFF_G  163840   // gates 64 x 17 floats = 4352
#define SMEM2  168448

__device__ __forceinline__ uint32_t swz(int row, int kbyte) {
    return (uint32_t)(row * 2048) + ((((uint32_t)kbyte >> 4) ^ (uint32_t)(row & 7)) << 4)
         + ((uint32_t)kbyte & 15u);
}

__global__ __launch_bounds__(NTHR, 1) void k_rnn(const float* __restrict__ h0,
                                                 const float* __restrict__ c0,
                                                 const float* __restrict__ mask,
                                                 const float* __restrict__ Wh,
                                                 float* __restrict__ out) {
    extern __shared__ char smraw[];
    const uint32_t smb = smem_u32(smraw);
    float* gates_s = (float*)(smraw + OFF_G);
    const int tid = threadIdx.x, lane = tid & 31, wid = tid >> 5;
    const int cta = blockIdx.x, hc0 = cta * 4;

    // ---- Wh slice -> B smem, split-bf16 (hi at kbyte<1024, lo >=1024) ----
#pragma unroll 4
    for (int it = 0; it < 32; it++) {
        int e = tid + it * NTHR;
        int n = e >> 10, k = e & 1023;
        int gcol = (n >> 2) * HID + hc0 + (n & 3);
        float v = Wh[(size_t)(k & 511) * GDIM + gcol];
        __nv_bfloat16 hi = __float2bfloat16_rn(v);
        __nv_bfloat16 bv = (k < 512) ? hi : __float2bfloat16_rn(v - __bfloat162float(hi));
        *(__nv_bfloat16*)(smraw + OFF_B + swz(n, k * 2)) = bv;
    }

    // MMA warp coords (wid < 8)
    const int mt = wid & 3, nt = wid >> 2;
    const int ar = mt * 16 + (lane & 15);
    const uint32_t aRowBase = smb + OFF_A + (uint32_t)ar * 2048;
    const uint32_t sA = (uint32_t)(ar & 7) << 4;
    const uint32_t aHi = (uint32_t)((lane >> 4) & 1) << 4;
    const int br = nt * 8 + (lane & 7);
    const uint32_t bRowBase = smb + OFF_B + (uint32_t)br * 2048;
    const uint32_t sB = (uint32_t)(br & 7) << 4;
    const uint32_t bQ = (uint32_t)((lane >> 3) & 3) << 4;   // x4: 4 groups of 16B

    // staging coords: one row per 8 threads, 16 x 16B units each (linear)
    const int strow = tid >> 3;
    const int stj   = tid & 7;
    const uint32_t stdst0 = smb + OFF_A + (uint32_t)(strow * 2048)
                          + ((uint32_t)(stj ^ (strow & 7)) << 4);
    const __nv_bfloat16* sthi = g_hhi + strow * HID + stj * 8;
    const __nv_bfloat16* stlo = g_hlo + strow * HID + stj * 8;

    // update mapping (first 256 threads)
    const int ub = tid >> 2;
    const int uj = tid & 3;
    float c_reg = 0.0f, h_pend = 0.0f;   // h_pend: deferred out value
    if (tid < 256) c_reg = c0[ub * HID + hc0 + uj];
    float* const outp = out + (size_t)ub * HID + hc0 + uj;   // step 0 slot

    unsigned int bar_target = 0;
    if (tid == 0) bar_target = *((volatile unsigned int*)&g_bar_gen);
    __syncthreads();

    for (int t = 0; t < T_STEPS; t++) {
        // deferred out store for step t-1 (overlaps staging; off release path)
        if (tid < 256 && t > 0)
            outp[(size_t)(t - 1) * BATCH * HID] = h_pend;

        // xp prefetch (DRAM latency overlaps staging)
        float xpi = 0, xpf = 0, xpg = 0, xpo = 0;
        if (tid < 256) {
            const float* xp = g_xproj + ((size_t)t * BATCH + ub) * GDIM + hc0 + uj;
            xpi = xp[0]; xpf = xp[HID]; xpg = xp[2 * HID]; xpo = xp[3 * HID];
        }
        const float* mrow = mask + t * BATCH;

        // ---- stage h into A smem ----
        if (t == 0) {
#pragma unroll
            for (int it = 0; it < 16; it++) {
                int idx = tid + it * NTHR;
                int row = idx >> 7, f4 = idx & 127;
                float4 v = *(const float4*)(h0 + (size_t)row * HID + f4 * 4);
                float kp = 1.0f - __ldg(&mrow[row]);
                v.x *= kp; v.y *= kp; v.z *= kp; v.w *= kp;
                __nv_bfloat162 h01 = __float22bfloat162_rn(make_float2(v.x, v.y));
                __nv_bfloat162 h23 = __float22bfloat162_rn(make_float2(v.z, v.w));
                float2 f01 = __bfloat1622float2(h01);
                float2 f23 = __bfloat1622float2(h23);
                __nv_bfloat162 l01 = __float22bfloat162_rn(make_float2(v.x - f01.x, v.y - f01.y));
                __nv_bfloat162 l23 = __float22bfloat162_rn(make_float2(v.z - f23.x, v.w - f23.y));
                uint2 hv, lv;
                hv.x = *(uint32_t*)&h01; hv.y = *(uint32_t*)&h23;
                lv.x = *(uint32_t*)&l01; lv.y = *(uint32_t*)&l23;
                *(uint2*)(smraw + OFF_A + swz(row, f4 * 8))        = hv;
                *(uint2*)(smraw + OFF_A + swz(row, 1024 + f4 * 8)) = lv;
            }
        } else {
            float mval = __ldg(&mrow[strow]);
            uint32_t d = stdst0;
#pragma unroll
            for (int i = 0; i < 8; i++) { CP_ASYNC16(d, sthi + i * 64); d += 128; }
#pragma unroll
            for (int i = 0; i < 8; i++) { CP_ASYNC16(d, stlo + i * 64); d += 128; }
            CP_COMMIT();
            CP_WAIT(0);
            if (mval != 0.0f) {
                uint4 z = {0u, 0u, 0u, 0u};
                uint32_t dz = stdst0;
#pragma unroll
                for (int i = 0; i < 16; i++) {
                    asm volatile("st.shared.v4.b32 [%0], {%1,%2,%3,%4};"
                                 :: "r"(dz), "r"(z.x), "r"(z.y), "r"(z.z), "r"(z.w));
                    dz += 128;
                }
            }
        }
        __syncthreads();

        // ---- MMA: 3 terms x 32 kc; kc paired, dual accumulators ----
        if (wid < 8) {
            float d0[4] = {0.f, 0.f, 0.f, 0.f};
            float d1[4] = {0.f, 0.f, 0.f, 0.f};
#pragma unroll
            for (int term = 0; term < 3; term++) {
                const uint32_t aOff = (term == 1) ? 1024u : 0u;
                const uint32_t bOff = (term == 2) ? 1024u : 0u;
#pragma unroll 4
                for (int kc = 0; kc < 32; kc += 2) {
                    uint32_t kb = (uint32_t)kc << 5;
                    uint32_t a0r[4], a1r[4], b0, b1, b2, b3;
                    LDSM_X4(a0r[0], a0r[1], a0r[2], a0r[3],
                            aRowBase + ((aOff + kb + aHi) ^ sA));
                    LDSM_X4(a1r[0], a1r[1], a1r[2], a1r[3],
                            aRowBase + ((aOff + kb + 32u + aHi) ^ sA));
                    LDSM_X4(b0, b1, b2, b3,
                            bRowBase + ((bOff + kb + bQ) ^ sB));
                    MMA16816(d0, a0r, b0, b1);
                    MMA16816(d1, a1r, b2, b3);
                }
            }
#pragma unroll
            for (int q = 0; q < 4; q++) d0[q] += d1[q];
            int gr = mt * 16 + (lane >> 2);
            int gc = nt * 8 + (lane & 3) * 2;
            gates_s[gr * 17 + gc]           = d0[0];
            gates_s[gr * 17 + gc + 1]       = d0[1];
            gates_s[(gr + 8) * 17 + gc]     = d0[2];
            gates_s[(gr + 8) * 17 + gc + 1] = d0[3];
        }
        __syncthreads();

        // ---- LSTM cell update: h planes stored NOW, out deferred ----
        if (tid < 256) {
            float kp = 1.0f - __ldg(&mrow[ub]);
            float gi = gates_s[ub * 17 + 0  + uj] + xpi;
            float gf = gates_s[ub * 17 + 4  + uj] + xpf;
            float gg = gates_s[ub * 17 + 8  + uj] + xpg;
            float go = gates_s[ub * 17 + 12 + uj] + xpo;
            float cprev = c_reg * kp;
            float cn = fsig(gf) * cprev + fsig(gi) * ftanh_(gg);
            float hn = fsig(go) * ftanh_(cn);
            c_reg = cn;
            int hcol = hc0 + uj;
            __nv_bfloat16 hh = __float2bfloat16_rn(hn);
            g_hhi[ub * HID + hcol] = hh;
            g_hlo[ub * HID + hcol] = __float2bfloat16_rn(hn - __bfloat162float(hh));
            h_pend = hn;               // out write deferred past the barrier
        }

        // ---- grid barrier: central counter, tid0-only polling ----
        __syncthreads();
        if (tid == 0) {
            bar_target += 1;
            unsigned int old;
            asm volatile("atom.add.acq_rel.gpu.u32 %0, [%1], 1;"
                         : "=r"(old) : "l"(&g_bar_count) : "memory");
            if (old == NCTA - 1) {
                asm volatile("st.relaxed.gpu.u32 [%0], 0;" :: "l"(&g_bar_count) : "memory");
                asm volatile("red.add.release.gpu.u32 [%0], 1;" :: "l"(&g_bar_gen) : "memory");
            } else {
                unsigned int g;
                while (1) {
                    asm volatile("ld.acquire.gpu.u32 %0, [%1];"
                                 : "=r"(g) : "l"(&g_bar_gen) : "memory");
                    if ((int)(g - bar_target) >= 0) break;
                    __nanosleep(20);
                }
            }
        }
        __syncthreads();
    }

    // Finals + flush last deferred out store
    if (tid < 256) {
        outp[(size_t)(T_STEPS - 1) * BATCH * HID] = h_pend;
        float* hfin = out + (size_t)T_STEPS * BATCH * HID;
        float* cfin = hfin + BATCH * HID;
        hfin[ub * HID + hc0 + uj] = h_pend;
        cfin[ub * HID + hc0 + uj] = c_reg;
    }
}

// =====================================================================
extern "C" void kernel_launch(void* const* d_in, const int* in_sizes, int n_in,
                              void* d_out, int out_size) {
    (void)in_sizes; (void)n_in; (void)out_size;
    const float* x    = (const float*)d_in[0];
    const float* h0   = (const float*)d_in[1];
    const float* c0   = (const float*)d_in[2];
    const float* mask = (const float*)d_in[3];
    const float* Wx   = (const float*)d_in[4];
    const float* Wh   = (const float*)d_in[5];
    const float* b    = (const float*)d_in[6];
    float* out = (float*)d_out;

    k_convert_x<<<MROWS * DDIM / 4 / 256, 256>>>(x);
    k_convert_w<<<dim3(GDIM / 32, DDIM / 32), 256>>>(Wx);

    cudaFuncSetAttribute(k_xproj_hmma, cudaFuncAttributeMaxDynamicSharedMemorySize, XSMEM);
    k_xproj_hmma<<<dim3(GDIM / 128, MROWS / 128), 256, XSMEM>>>(b);

    cudaFuncSetAttribute(k_rnn, cudaFuncAttributeMaxDynamicSharedMemorySize, SMEM2);
    k_rnn<<<NCTA, NTHR, SMEM2>>>(h0, c0, mask, Wh, out);
}